// round 15
// baseline (speedup 1.0000x reference)
#include <cuda_runtime.h>
#include <cuda_bf16.h>

// Shapes (fixed):
//   emb_nodes : [B=4, N=768, d=16] f32   (d_in[0])
//   edges     : [B=4, 2, E=12288]  i32   (d_in[1])
//   W         : [32] f32                 (d_in[2])
//   b         : [1]  f32                 (d_in[3])
// d_out (f32): ee [4,589824,32] @0 | logits [4,589824] @75497472 | truth @77856768

namespace {
constexpr unsigned B_  = 4;
constexpr unsigned N_  = 768;
constexpr unsigned E_  = 12288;
constexpr unsigned NN_    = N_ * N_;          // 589824
constexpr unsigned PAIRS_ = B_ * NN_;         // 2359296
constexpr unsigned NODES_ = B_ * N_;          // 3072
constexpr unsigned BM_WORDS_ = PAIRS_ / 32;   // 73728 (288 KB bitmap)
constexpr unsigned long long EE_ELEMS_ = (unsigned long long)PAIRS_ * 32; // 75497472
}

// Device-global scratch (no allocation allowed).
__device__ float    g_dot1[NODES_];     // e_v . W[0:16] + bias
__device__ float    g_dot2[NODES_];     // e_v . W[16:32]
__device__ unsigned g_hash[NODES_];     // row-bit hash (0-canonicalized)
// Ground-truth bitmap: zero at module load; mega self-clears after reading,
// so every kernel_launch starts from zero (graph-replay deterministic).
__device__ unsigned g_bitmap[BM_WORDS_];

// ---------------------------------------------------------------------------
// Kernel 1: edge scatter into bitmap + per-node dots/hash (disjoint ranges).
// ---------------------------------------------------------------------------
__global__ __launch_bounds__(256)
void scatter_pre_kernel(const int*    __restrict__ edges,
                        const float4* __restrict__ emb4,
                        const float4* __restrict__ W4,
                        const float*  __restrict__ bias)
{
    unsigned t = blockIdx.x * blockDim.x + threadIdx.x;

    if (t < B_ * E_) {
        unsigned b = t / E_;
        unsigned e = t - b * E_;
        unsigned src = (unsigned)edges[b * 2 * E_ + e];
        unsigned dst = (unsigned)edges[b * 2 * E_ + E_ + e];
        unsigned pair = b * NN_ + src * N_ + dst;
        atomicOr(&g_bitmap[pair >> 5], 1u << (pair & 31));
    }

    if (t < NODES_) {
        float d1 = __ldg(bias);
        float d2 = 0.f;
        unsigned h = 0u;
        #pragma unroll
        for (int c = 0; c < 4; ++c) {
            float4 a  = __ldg(emb4 + t * 4u + c);
            float4 w1 = __ldg(W4 + c);
            float4 w2 = __ldg(W4 + c + 4);
            d1 = fmaf(a.x, w1.x, d1); d1 = fmaf(a.y, w1.y, d1);
            d1 = fmaf(a.z, w1.z, d1); d1 = fmaf(a.w, w1.w, d1);
            d2 = fmaf(a.x, w2.x, d2); d2 = fmaf(a.y, w2.y, d2);
            d2 = fmaf(a.z, w2.z, d2); d2 = fmaf(a.w, w2.w, d2);
            const float vals[4] = {a.x, a.y, a.z, a.w};
            #pragma unroll
            for (int k = 0; k < 4; ++k) {
                unsigned u = __float_as_uint(vals[k]);
                if (vals[k] == 0.f) u = 0u;          // canonicalize +-0
                int rot = (c * 4 + k) & 31;
                h ^= __funnelshift_l(u, u, rot);
            }
        }
        g_dot1[t] = d1;
        g_dot2[t] = d2;
        g_hash[t] = h;
    }
}

// exact row comparison under float== (rare path: hash matched)
__device__ __forceinline__ bool rows_equal(const float4* __restrict__ emb4,
                                           unsigned va, unsigned vb)
{
    bool eq = true;
    #pragma unroll
    for (int c = 0; c < 4; ++c) {
        float4 a = __ldg(emb4 + va * 4u + c);
        float4 b = __ldg(emb4 + vb * 4u + c);
        eq = eq && (a.x == b.x) && (a.y == b.y) && (a.z == b.z) && (a.w == b.w);
    }
    return eq;
}

// ---------------------------------------------------------------------------
// Kernel 2 (mega, flat): grid = 73728 blocks x 256. Each thread copies ONE
// float4 of ee (R8 shape: 8 consecutive threads = one 128B pair line).
// Each block covers exactly 32 pairs of one row i and exactly one bitmap
// word (word index == blockIdx.x). Warp 0 micro-tail:
//   tid 0..7  -> logits float4 for pairs j0+4*tid..+3
//   tid 8..15 -> truth  float4 from bitmap word bits
//   tid 8     -> clears the word after __syncwarp.
// ---------------------------------------------------------------------------
__global__ __launch_bounds__(256)
void mega_kernel(const float4* __restrict__ emb4,
                 float4* __restrict__ ee4,
                 float4* __restrict__ logits4,
                 float4* __restrict__ truth4)
{
    unsigned blk = blockIdx.x;                 // 0 .. 73727
    unsigned tid = threadIdx.x;

    unsigned pair0 = blk * 32u;                // first pair of this block
    unsigned b     = pair0 / NN_;
    unsigned rem   = pair0 - b * NN_;
    unsigned i     = rem / N_;
    unsigned j0    = rem - i * N_;             // multiple of 32

    // ---- micro-tail first (latency hides under the copy stores) ----
    if (tid < 16u) {
        if (tid < 8u) {
            unsigned ni = b * N_ + i;
            float    d1 = g_dot1[ni];
            unsigned hi = g_hash[ni];

            unsigned nj = b * N_ + j0 + tid * 4u;
            float4 d2 = *(const float4*)&g_dot2[nj];
            uint4  hj = *(const uint4*)&g_hash[nj];

            float lg[4] = { d1 + d2.x, d1 + d2.y, d1 + d2.z, d1 + d2.w };
            const unsigned hjs[4] = { hj.x, hj.y, hj.z, hj.w };
            #pragma unroll
            for (int q = 0; q < 4; ++q) {
                if (hi == hjs[q]) {            // rare: verify exactly
                    if (rows_equal(emb4, ni, nj + q)) lg[q] = -10.0f;
                }
            }
            __stcs(logits4 + (pair0 >> 2) + tid,
                   make_float4(lg[0], lg[1], lg[2], lg[3]));
        } else {
            unsigned w    = g_bitmap[blk];     // block-owned word (32 pairs)
            unsigned bit0 = (tid - 8u) * 4u;
            float4 tr = make_float4((float)((w >> (bit0 + 0)) & 1u),
                                    (float)((w >> (bit0 + 1)) & 1u),
                                    (float)((w >> (bit0 + 2)) & 1u),
                                    (float)((w >> (bit0 + 3)) & 1u));
            __stcs(truth4 + (pair0 >> 2) + (tid - 8u), tr);
        }
        __syncwarp(0x0000FFFFu);
        if (tid == 8u) g_bitmap[blk] = 0u;     // self-clear for next replay
    }

    // ---- ee copy: one float4 per thread (256 float4 = 32 pairs) ----
    unsigned f     = tid;                      // 0..255 within block
    unsigned jloc  = f >> 3;                   // 0..31
    unsigned chunk = f & 7u;
    unsigned node  = (chunk < 4u) ? i : (j0 + jloc);
    float4 v = __ldg(emb4 + (b * N_ + node) * 4u + (chunk & 3u));
    __stcs(ee4 + (unsigned long long)pair0 * 8u + f, v);
}

extern "C" void kernel_launch(void* const* d_in, const int* in_sizes, int n_in,
                              void* d_out, int out_size)
{
    const float* emb   = (const float*)d_in[0];
    const int*   edges = (const int*)d_in[1];
    const float* W     = (const float*)d_in[2];
    const float* bias  = (const float*)d_in[3];

    float* out    = (float*)d_out;
    float* ee     = out;
    float* logits = out + EE_ELEMS_;
    float* truth  = out + EE_ELEMS_ + PAIRS_;

    // 1. fused edge scatter + node precompute (49152 threads)
    scatter_pre_kernel<<<(B_ * E_) / 256, 256>>>(edges, (const float4*)emb,
                                                 (const float4*)W, bias);
    // 2. mega (flat): all 321MB of output + bitmap self-clear
    mega_kernel<<<BM_WORDS_, 256>>>((const float4*)emb, (float4*)ee,
                                    (float4*)logits, (float4*)truth);
}

// round 16
// speedup vs baseline: 1.4545x; 1.4545x over previous
#include <cuda_runtime.h>
#include <cuda_bf16.h>

// Shapes (fixed):
//   emb_nodes : [B=4, N=768, d=16] f32   (d_in[0])
//   edges     : [B=4, 2, E=12288]  i32   (d_in[1])
//   W         : [32] f32                 (d_in[2])
//   b         : [1]  f32                 (d_in[3])
// d_out (f32): ee [4,589824,32] @0 | logits [4,589824] @75497472 | truth @77856768

namespace {
constexpr unsigned B_  = 4;
constexpr unsigned N_  = 768;
constexpr unsigned E_  = 12288;
constexpr unsigned NN_    = N_ * N_;          // 589824
constexpr unsigned PAIRS_ = B_ * NN_;         // 2359296
constexpr unsigned NODES_ = B_ * N_;          // 3072
constexpr unsigned BM_WORDS_ = PAIRS_ / 32;   // 73728 (288 KB bitmap)
constexpr unsigned COPY_BLKS_ = PAIRS_ * 8 / 256;   // 73728
constexpr unsigned TAIL_BLKS_ = PAIRS_ / 4 / 256;   // 2304
constexpr unsigned long long EE_ELEMS_ = (unsigned long long)PAIRS_ * 32; // 75497472
}

// Device-global scratch (no allocation allowed).
__device__ float    g_dot1[NODES_];     // e_v . W[0:16] + bias
__device__ float    g_dot2[NODES_];     // e_v . W[16:32]
__device__ unsigned g_hash[NODES_];     // row-bit hash (0-canonicalized)
// Ground-truth bitmap: zero at module load; tail blocks self-clear after
// reading, so every kernel_launch starts from zero (graph-replay safe).
__device__ unsigned g_bitmap[BM_WORDS_];

// ---------------------------------------------------------------------------
// Kernel 1: edge scatter into bitmap + per-node dots/hash (disjoint ranges).
// ---------------------------------------------------------------------------
__global__ __launch_bounds__(256)
void scatter_pre_kernel(const int*    __restrict__ edges,
                        const float4* __restrict__ emb4,
                        const float4* __restrict__ W4,
                        const float*  __restrict__ bias)
{
    unsigned t = blockIdx.x * blockDim.x + threadIdx.x;

    if (t < B_ * E_) {
        unsigned b = t / E_;
        unsigned e = t - b * E_;
        unsigned src = (unsigned)edges[b * 2 * E_ + e];
        unsigned dst = (unsigned)edges[b * 2 * E_ + E_ + e];
        unsigned pair = b * NN_ + src * N_ + dst;
        atomicOr(&g_bitmap[pair >> 5], 1u << (pair & 31));
    }

    if (t < NODES_) {
        float d1 = __ldg(bias);
        float d2 = 0.f;
        unsigned h = 0u;
        #pragma unroll
        for (int c = 0; c < 4; ++c) {
            float4 a  = __ldg(emb4 + t * 4u + c);
            float4 w1 = __ldg(W4 + c);
            float4 w2 = __ldg(W4 + c + 4);
            d1 = fmaf(a.x, w1.x, d1); d1 = fmaf(a.y, w1.y, d1);
            d1 = fmaf(a.z, w1.z, d1); d1 = fmaf(a.w, w1.w, d1);
            d2 = fmaf(a.x, w2.x, d2); d2 = fmaf(a.y, w2.y, d2);
            d2 = fmaf(a.z, w2.z, d2); d2 = fmaf(a.w, w2.w, d2);
            const float vals[4] = {a.x, a.y, a.z, a.w};
            #pragma unroll
            for (int k = 0; k < 4; ++k) {
                unsigned u = __float_as_uint(vals[k]);
                if (vals[k] == 0.f) u = 0u;          // canonicalize +-0
                int rot = (c * 4 + k) & 31;
                h ^= __funnelshift_l(u, u, rot);
            }
        }
        g_dot1[t] = d1;
        g_dot2[t] = d2;
        g_hash[t] = h;
    }
}

// exact row comparison under float== (rare path: hash matched)
__device__ __forceinline__ bool rows_equal(const float4* __restrict__ emb4,
                                           unsigned va, unsigned vb)
{
    bool eq = true;
    #pragma unroll
    for (int c = 0; c < 4; ++c) {
        float4 a = __ldg(emb4 + va * 4u + c);
        float4 b = __ldg(emb4 + vb * 4u + c);
        eq = eq && (a.x == b.x) && (a.y == b.y) && (a.z == b.z) && (a.w == b.w);
    }
    return eq;
}

// ---------------------------------------------------------------------------
// Kernel 2 (mega): disjoint block roles.
//   blocks [0, 73728)       : pure flat ee copy (R8 shape, 1 LDG+1 STG/thread)
//   blocks [73728, 76032)   : logits + truth + bitmap self-clear
// ---------------------------------------------------------------------------
__global__ __launch_bounds__(256, 8)
void mega_kernel(const float4* __restrict__ emb4,
                 float4* __restrict__ ee4,
                 float4* __restrict__ logits4,
                 float4* __restrict__ truth4)
{
    unsigned blk = blockIdx.x;
    unsigned tid = threadIdx.x;

    if (blk < COPY_BLKS_) {
        // ---- pure copy: one float4 per thread; 8 threads = one pair line ----
        unsigned t     = blk * 256u + tid;     // < PAIRS_*8
        unsigned pair  = t >> 3;
        unsigned chunk = t & 7u;

        unsigned b   = pair / NN_;
        unsigned rem = pair - b * NN_;
        unsigned i   = rem / N_;
        unsigned j   = rem - i * N_;

        unsigned node = (chunk < 4u) ? i : j;
        float4 v = __ldg(emb4 + (b * N_ + node) * 4u + (chunk & 3u));
        __stcs(ee4 + (unsigned long long)pair * 8u + chunk, v);
    } else {
        // ---- tail: one thread per 4 consecutive pairs ----
        unsigned t = (blk - COPY_BLKS_) * 256u + tid;   // < PAIRS_/4
        unsigned pair0 = t * 4u;
        unsigned b   = pair0 / NN_;
        unsigned rem = pair0 - b * NN_;
        unsigned i   = rem / N_;
        unsigned j0  = rem - i * N_;

        unsigned ni = b * N_ + i;
        float    d1 = g_dot1[ni];
        unsigned hi = g_hash[ni];

        unsigned nj = b * N_ + j0;
        float4 d2 = *(const float4*)&g_dot2[nj];
        uint4  hj = *(const uint4*)&g_hash[nj];

        float lg[4] = { d1 + d2.x, d1 + d2.y, d1 + d2.z, d1 + d2.w };
        const unsigned hjs[4] = { hj.x, hj.y, hj.z, hj.w };
        #pragma unroll
        for (int q = 0; q < 4; ++q) {
            if (hi == hjs[q]) {                // rare: verify exactly
                if (rows_equal(emb4, ni, nj + q)) lg[q] = -10.0f;
            }
        }

        unsigned widx = pair0 >> 5;            // 8 threads share one word
        unsigned w    = g_bitmap[widx];
        unsigned bit0 = pair0 & 31u;
        float4 tr = make_float4((float)((w >> (bit0 + 0)) & 1u),
                                (float)((w >> (bit0 + 1)) & 1u),
                                (float)((w >> (bit0 + 2)) & 1u),
                                (float)((w >> (bit0 + 3)) & 1u));

        __stcs(logits4 + t, make_float4(lg[0], lg[1], lg[2], lg[3]));
        __stcs(truth4 + t, tr);

        // self-clear bitmap word for the next graph replay
        __syncwarp();
        if ((t & 7u) == 0u) g_bitmap[widx] = 0u;
    }
}

extern "C" void kernel_launch(void* const* d_in, const int* in_sizes, int n_in,
                              void* d_out, int out_size)
{
    const float* emb   = (const float*)d_in[0];
    const int*   edges = (const int*)d_in[1];
    const float* W     = (const float*)d_in[2];
    const float* bias  = (const float*)d_in[3];

    float* out    = (float*)d_out;
    float* ee     = out;
    float* logits = out + EE_ELEMS_;
    float* truth  = out + EE_ELEMS_ + PAIRS_;

    // 1. fused edge scatter + node precompute (49152 threads)
    scatter_pre_kernel<<<(B_ * E_) / 256, 256>>>(edges, (const float4*)emb,
                                                 (const float4*)W, bias);
    // 2. mega: copy blocks + tail blocks in one launch
    mega_kernel<<<COPY_BLKS_ + TAIL_BLKS_, 256>>>((const float4*)emb,
                                                  (float4*)ee,
                                                  (float4*)logits,
                                                  (float4*)truth);
}